// round 6
// baseline (speedup 1.0000x reference)
#include <cuda_runtime.h>

// Problem constants
#define N_    64
#define C_    64
#define T_    300
#define V_    25
#define IC_   16
#define NS_   3

typedef unsigned long long ull;

__device__ __forceinline__ ull dup2(float v) {
    ull r; asm("mov.b64 %0, {%1, %1};" : "=l"(r) : "f"(v)); return r;
}
__device__ __forceinline__ void fma2(ull& acc, ull a, ull b) {
    asm("fma.rn.f32x2 %0, %1, %2, %0;" : "+l"(acc) : "l"(a), "l"(b));
}
__device__ __forceinline__ void unpack2(ull v, float& lo, float& hi) {
    asm("mov.b64 {%0, %1}, %2;" : "=f"(lo), "=f"(hi) : "l"(v));
}

// Intermediate M buffer: M[s][n][t][v]
__device__ float g_M[NS_ * N_ * T_ * V_];

// ======================= Kernel A: attention -> M =======================
#define TCA   4
#define COLSA 100          // TCA * V_
#define NTA   200
#define GRIDA (N_ * (T_ / TCA))   // 4800

struct SmemA {
    float WabT[NS_][64][32];   // [s][c][r]  r<16: a_w, r>=16: b_w   24576 B
    float xs[64][COLSA];       // 25600 B (row 400B, 16B aligned)
    float CaCb[32][TCA * 28];  // 14336 B
    float Pm[TCA][25][26];     // 10400 B
    float colA[NS_][32];
    float absh[NS_][32];
};

__global__ void __launch_bounds__(NTA, 3)
tsagc_attn_kernel(const float* __restrict__ x,
                  const float* __restrict__ A,
                  const float* __restrict__ GA,
                  const float* __restrict__ a_w,
                  const float* __restrict__ a_b,
                  const float* __restrict__ b_w,
                  const float* __restrict__ b_b)
{
    extern __shared__ float smem_raw[];
    SmemA& sm = *reinterpret_cast<SmemA*>(smem_raw);
    const int tid = threadIdx.x;

    // ---- stage weights ----
    for (int idx = tid; idx < NS_ * IC_ * 64; idx += NTA) {
        int c  = idx & 63;
        int ic = (idx >> 6) & 15;
        int s  = idx >> 10;
        sm.WabT[s][c][ic]      = a_w[idx];
        sm.WabT[s][c][16 + ic] = b_w[idx];
    }
    for (int idx = tid; idx < NS_ * IC_; idx += NTA) {
        int s = idx / IC_, ic = idx % IC_;
        sm.absh[s][ic]      = a_b[idx];
        sm.absh[s][16 + ic] = b_b[idx];
    }
    for (int idx = tid; idx < NS_ * V_; idx += NTA) {
        int s = idx / V_, v = idx % V_;
        float acc = 0.f;
        #pragma unroll 5
        for (int a = 0; a < V_; a++) {
            int off = (s * V_ + a) * V_ + v;
            acc += A[off] + GA[off];
        }
        sm.colA[s][v] = acc;
    }
    // zero CaCb pad columns v=25..27
    for (int idx = tid; idx < 32 * TCA * 3; idx += NTA) {
        int r = idx / (TCA * 3);
        int q = idx % (TCA * 3);
        sm.CaCb[r][(q / 3) * 28 + 25 + (q % 3)] = 0.f;
    }

    // ---- load x chunk (t0 multiple of 4 -> float4 aligned) ----
    const int n  = blockIdx.x / (T_ / TCA);
    const int t0 = (blockIdx.x % (T_ / TCA)) * TCA;
    const float* xg = x + (n * 64 * T_ + t0) * V_;
    for (int idx = tid; idx < 64 * (COLSA / 4); idx += NTA) {
        int c = idx / (COLSA / 4), q = idx % (COLSA / 4);
        float4 val = *reinterpret_cast<const float4*>(xg + c * (T_ * V_) + q * 4);
        *reinterpret_cast<float4*>(&sm.xs[c][q * 4]) = val;
    }
    __syncthreads();

    const int rg   = tid / 50;     // 0..3, rows r0 = rg*8 (4 pairs)
    const int cg   = tid % 50;     // 0..49
    const int col0 = cg * 2;

    int tcv[2], vv[2];
    #pragma unroll
    for (int j = 0; j < 2; j++) {
        int col = col0 + j;
        tcv[j] = col / 25;
        vv[j]  = col - tcv[j] * 25;
    }

    for (int s = 0; s < NS_; s++) {
        // ---- Phase 1: CaCb = Wab[s] @ xs  (8 rows x 2 cols, pairs on r) ----
        {
            const int r0 = rg * 8;
            ull acc2[4][2];   // [row-pair][col]
            #pragma unroll
            for (int k = 0; k < 4; k++) { acc2[k][0] = 0ull; acc2[k][1] = 0ull; }
            #pragma unroll 2
            for (int c = 0; c < 64; c++) {
                ulonglong2 w01 = *reinterpret_cast<const ulonglong2*>(&sm.WabT[s][c][r0]);
                ulonglong2 w23 = *reinterpret_cast<const ulonglong2*>(&sm.WabT[s][c][r0 + 4]);
                float2 xv = *reinterpret_cast<const float2*>(&sm.xs[c][col0]);
                ull xd0 = dup2(xv.x), xd1 = dup2(xv.y);
                fma2(acc2[0][0], w01.x, xd0); fma2(acc2[0][1], w01.x, xd1);
                fma2(acc2[1][0], w01.y, xd0); fma2(acc2[1][1], w01.y, xd1);
                fma2(acc2[2][0], w23.x, xd0); fma2(acc2[2][1], w23.x, xd1);
                fma2(acc2[3][0], w23.y, xd0); fma2(acc2[3][1], w23.y, xd1);
            }
            #pragma unroll
            for (int k = 0; k < 4; k++) {
                float bA = sm.absh[s][r0 + 2 * k];
                float bB = sm.absh[s][r0 + 2 * k + 1];
                #pragma unroll
                for (int j = 0; j < 2; j++) {
                    float lo, hi;
                    unpack2(acc2[k][j], lo, hi);
                    sm.CaCb[r0 + 2 * k][tcv[j] * 28 + vv[j]]     = lo + bA;
                    sm.CaCb[r0 + 2 * k + 1][tcv[j] * 28 + vv[j]] = hi + bB;
                }
            }
        }
        __syncthreads();

        // ---- Phase 2a: logits + softmax (100 threads, 1 row each) ----
        if (tid < 100) {
            const int tc = tid / 25, a = tid % 25;
            const int tcBase = tc * 28;
            ull l2[13];
            #pragma unroll
            for (int p = 0; p < 13; p++) l2[p] = 0ull;
            #pragma unroll 4
            for (int ic = 0; ic < 16; ic++) {
                ull cad = dup2(sm.CaCb[ic][tcBase + a]);
                const ulonglong2* cb =
                    reinterpret_cast<const ulonglong2*>(&sm.CaCb[16 + ic][tcBase]);
                #pragma unroll
                for (int q = 0; q < 6; q++) {
                    ulonglong2 cv = cb[q];
                    fma2(l2[q * 2],     cad, cv.x);
                    fma2(l2[q * 2 + 1], cad, cv.y);
                }
                fma2(l2[12], cad, cb[6].x);
            }
            float l[26];
            #pragma unroll
            for (int p = 0; p < 13; p++) unpack2(l2[p], l[2 * p], l[2 * p + 1]);
            float mx = -1e30f;
            #pragma unroll
            for (int b = 0; b < 25; b++) { l[b] *= 0.0625f; mx = fmaxf(mx, l[b]); }
            float ssum = 0.f;
            #pragma unroll
            for (int b = 0; b < 25; b++) { float e = __expf(l[b] - mx); ssum += e; l[b] = e; }
            float inv = 1.f / ssum;
            float* pr = sm.Pm[tc][a];
            #pragma unroll
            for (int b = 0; b < 25; b++) pr[b] = l[b] * inv;
        }
        __syncthreads();

        // ---- Phase 2b: column sums -> g_M ----
        if (tid < 100) {
            const int tc = tid / 25, b = tid % 25;
            float msum = sm.colA[s][b];
            #pragma unroll 5
            for (int a = 0; a < 25; a++) msum += sm.Pm[tc][a][b];
            g_M[((s * N_ + n) * T_ + t0 + tc) * V_ + b] = msum;
        }
        __syncthreads();
    }
}

// ======================= Kernel B: output GEMM =======================
#define TCB   6
#define COLSB 150          // TCB * V_
#define NTB   300
#define GRIDB (N_ * (T_ / TCB))   // 3200

struct SmemB {
    float GT[NS_][64][64];     // [s][c][o]   49152 B
    float xs[64][COLSB];       // 38400 B (row 600B, 8B aligned)
    float Msm[NS_][COLSB];     // 1800 B
    float scArr[64];
    float shArr[64];
};

__global__ void __launch_bounds__(NTB, 2)
tsagc_out_kernel(const float* __restrict__ x,
                 const float* __restrict__ g_w,
                 const float* __restrict__ g_b,
                 const float* __restrict__ bn_gamma,
                 const float* __restrict__ bn_beta,
                 const float* __restrict__ bn_mean,
                 const float* __restrict__ bn_var,
                 float* __restrict__ out)
{
    extern __shared__ float smem_raw[];
    SmemB& sm = *reinterpret_cast<SmemB*>(smem_raw);
    const int tid = threadIdx.x;

    // ---- stage GT (g_w transposed) ----
    for (int idx = tid; idx < NS_ * 64 * 64; idx += NTB) {
        int c = idx & 63;
        int o = (idx >> 6) & 63;
        int s = idx >> 12;
        sm.GT[s][c][o] = g_w[idx];
    }
    if (tid < 64) {
        float inv = rsqrtf(bn_var[tid] + 1e-5f);
        float scv = bn_gamma[tid] * inv;
        sm.scArr[tid] = scv;
        float cb = g_b[tid] + g_b[64 + tid] + g_b[128 + tid];
        sm.shArr[tid] = (cb - bn_mean[tid]) * scv + bn_beta[tid];
    }

    const int n  = blockIdx.x / (T_ / TCB);
    const int t0 = (blockIdx.x % (T_ / TCB)) * TCB;

    // ---- load x chunk (float2: t0*25 even) ----
    const float* xg = x + (n * 64 * T_ + t0) * V_;
    for (int idx = tid; idx < 64 * (COLSB / 2); idx += NTB) {
        int c = idx / (COLSB / 2), q = idx % (COLSB / 2);
        float2 val = *reinterpret_cast<const float2*>(xg + c * (T_ * V_) + q * 2);
        *reinterpret_cast<float2*>(&sm.xs[c][q * 2]) = val;
    }
    // ---- load M chunk ----
    for (int idx = tid; idx < NS_ * (COLSB / 2); idx += NTB) {
        int s = idx / (COLSB / 2), q = idx % (COLSB / 2);
        float2 val = *reinterpret_cast<const float2*>(
            &g_M[(s * N_ + n) * (T_ * V_) + t0 * V_ + q * 2]);
        *reinterpret_cast<float2*>(&sm.Msm[s][q * 2]) = val;
    }
    __syncthreads();

    // ---- mainloop: 16 rows (8 o-pairs) x 2 cols per thread ----
    const int rg   = tid / 75;     // 0..3 -> o0 = rg*16
    const int cg   = tid % 75;     // 0..74
    const int col0 = cg * 2;
    const int o0   = rg * 16;

    float ms[NS_][2];
    #pragma unroll
    for (int s = 0; s < NS_; s++) {
        ms[s][0] = sm.Msm[s][col0];
        ms[s][1] = sm.Msm[s][col0 + 1];
    }

    ull acc2[8][2];   // [o-pair][col]
    #pragma unroll
    for (int k = 0; k < 8; k++) { acc2[k][0] = 0ull; acc2[k][1] = 0ull; }

    #pragma unroll 2
    for (int c = 0; c < 64; c++) {
        float2 xv = *reinterpret_cast<const float2*>(&sm.xs[c][col0]);
        #pragma unroll
        for (int s = 0; s < NS_; s++) {
            const ulonglong2* gp =
                reinterpret_cast<const ulonglong2*>(&sm.GT[s][c][o0]);
            ulonglong2 g01 = gp[0];   // pairs (o0+0,1), (o0+2,3)
            ulonglong2 g23 = gp[1];
            ulonglong2 g45 = gp[2];
            ulonglong2 g67 = gp[3];
            ull xm0 = dup2(xv.x * ms[s][0]);
            ull xm1 = dup2(xv.y * ms[s][1]);
            fma2(acc2[0][0], g01.x, xm0); fma2(acc2[0][1], g01.x, xm1);
            fma2(acc2[1][0], g01.y, xm0); fma2(acc2[1][1], g01.y, xm1);
            fma2(acc2[2][0], g23.x, xm0); fma2(acc2[2][1], g23.x, xm1);
            fma2(acc2[3][0], g23.y, xm0); fma2(acc2[3][1], g23.y, xm1);
            fma2(acc2[4][0], g45.x, xm0); fma2(acc2[4][1], g45.x, xm1);
            fma2(acc2[5][0], g45.y, xm0); fma2(acc2[5][1], g45.y, xm1);
            fma2(acc2[6][0], g67.x, xm0); fma2(acc2[6][1], g67.x, xm1);
            fma2(acc2[7][0], g67.y, xm0); fma2(acc2[7][1], g67.y, xm1);
        }
    }

    // ---- epilogue: BN + residual + ReLU ----
    #pragma unroll
    for (int k = 0; k < 8; k++) {
        int oa = o0 + 2 * k;
        int ob = oa + 1;
        float scA = sm.scArr[oa], shA = sm.shArr[oa];
        float scB = sm.scArr[ob], shB = sm.shArr[ob];
        float a0, b0, a1, b1;           // (row, col): a=row oa, b=row ob
        unpack2(acc2[k][0], a0, b0);    // col0
        unpack2(acc2[k][1], a1, b1);    // col0+1
        float2 xrA = *reinterpret_cast<const float2*>(&sm.xs[oa][col0]);
        float2 xrB = *reinterpret_cast<const float2*>(&sm.xs[ob][col0]);
        float2 resA, resB;
        resA.x = fmaxf(a0 * scA + shA + xrA.x, 0.f);
        resA.y = fmaxf(a1 * scA + shA + xrA.y, 0.f);
        resB.x = fmaxf(b0 * scB + shB + xrB.x, 0.f);
        resB.y = fmaxf(b1 * scB + shB + xrB.y, 0.f);
        float* opA = out + (n * 64 + oa) * (T_ * V_) + t0 * V_ + col0;
        float* opB = out + (n * 64 + ob) * (T_ * V_) + t0 * V_ + col0;
        *reinterpret_cast<float2*>(opA) = resA;
        *reinterpret_cast<float2*>(opB) = resB;
    }
}

extern "C" void kernel_launch(void* const* d_in, const int* in_sizes, int n_in,
                              void* d_out, int out_size)
{
    const float* x        = (const float*)d_in[0];
    const float* A        = (const float*)d_in[1];
    const float* GA       = (const float*)d_in[2];
    const float* g_w      = (const float*)d_in[3];
    const float* g_b      = (const float*)d_in[4];
    const float* a_w      = (const float*)d_in[5];
    const float* a_b      = (const float*)d_in[6];
    const float* b_w      = (const float*)d_in[7];
    const float* b_b      = (const float*)d_in[8];
    const float* bn_gamma = (const float*)d_in[9];
    const float* bn_beta  = (const float*)d_in[10];
    const float* bn_mean  = (const float*)d_in[11];
    const float* bn_var   = (const float*)d_in[12];
    float* out = (float*)d_out;

    static int configured = 0;
    size_t smemA = sizeof(SmemA);
    size_t smemB = sizeof(SmemB);
    cudaFuncSetAttribute(tsagc_attn_kernel,
                         cudaFuncAttributeMaxDynamicSharedMemorySize, (int)smemA);
    cudaFuncSetAttribute(tsagc_out_kernel,
                         cudaFuncAttributeMaxDynamicSharedMemorySize, (int)smemB);
    (void)configured;

    tsagc_attn_kernel<<<GRIDA, NTA, smemA>>>(x, A, GA, a_w, a_b, b_w, b_b);
    tsagc_out_kernel<<<GRIDB, NTB, smemB>>>(x, g_w, g_b, bn_gamma, bn_beta,
                                            bn_mean, bn_var, out);
}